// round 6
// baseline (speedup 1.0000x reference)
#include <cuda_runtime.h>
#include <cuda_bf16.h>
#include <cuda_fp16.h>
#include <cstdint>

#define SEQ    256
#define BATCH  32
#define REC    16
#define EMB    32
#define VOCAB  32000
#define NROWS  (SEQ * BATCH)   // 8192
#define VS     10              // vocab splits
#define NPAIR  (VOCAB / 16)    // 2000 column-pairs

// k_out tiling
#define RPB_O  32
#define NF_O   2
// k_sum tiling
#define RPB_S  64
#define NF_S   4

// ---- scratch ----
__device__ float          g_Apre[NROWS * REC];
__device__ __nv_bfloat16  g_hidden[NROWS * REC];
__device__ __nv_bfloat16  g_hiddenL[NROWS * REC];   // hidden * log2(e)
__device__ uint4          g_Vq[NPAIR * 8 * 4];      // permuted V
__device__ float          g_part[VS][NROWS];

__device__ __forceinline__ float ex2f(float x) { float y; asm("ex2.approx.f32 %0, %1;" : "=f"(y) : "f"(x)); return y; }
__device__ __forceinline__ float lg2f(float x) { float y; asm("lg2.approx.f32 %0, %1;" : "=f"(y) : "f"(x)); return y; }
__device__ __forceinline__ float rcpf(float x) { float y; asm("rcp.approx.f32 %0, %1;" : "=f"(y) : "f"(x)); return y; }

#define L2E 1.4426950408889634f
#define LN2 0.6931471805599453f

__device__ __forceinline__ void mma16816(float d[4], const uint32_t a[4], uint32_t b0, uint32_t b1) {
    asm("mma.sync.aligned.m16n8k16.row.col.f32.bf16.bf16.f32 "
        "{%0,%1,%2,%3}, {%4,%5,%6,%7}, {%8,%9}, {%10,%11,%12,%13};"
        : "=f"(d[0]), "=f"(d[1]), "=f"(d[2]), "=f"(d[3])
        : "r"(a[0]), "r"(a[1]), "r"(a[2]), "r"(a[3]),
          "r"(b0), "r"(b1),
          "f"(0.0f), "f"(0.0f), "f"(0.0f), "f"(0.0f));
}

// MMA with accumulator pre-initialized to (-cl, -cl, -ch, -ch): d = A*B - c
__device__ __forceinline__ void mma16816c(float d[4], const uint32_t a[4], uint32_t b0, uint32_t b1,
                                          float ncl, float nch) {
    asm("mma.sync.aligned.m16n8k16.row.col.f32.bf16.bf16.f32 "
        "{%0,%1,%2,%3}, {%4,%5,%6,%7}, {%8,%9}, {%10,%11,%12,%13};"
        : "=f"(d[0]), "=f"(d[1]), "=f"(d[2]), "=f"(d[3])
        : "r"(a[0]), "r"(a[1]), "r"(a[2]), "r"(a[3]),
          "r"(b0), "r"(b1),
          "f"(ncl), "f"(ncl), "f"(nch), "f"(nch));
}

// 2^x, 2^y as half2 via one pack + one MUFU
__device__ __forceinline__ __half2 h2ex2(float x, float y) {
    uint32_t u, r;
    asm("cvt.rn.f16x2.f32 %0, %1, %2;" : "=r"(u) : "f"(y), "f"(x));
    asm("ex2.approx.f16x2 %0, %1;" : "=r"(r) : "r"(u));
    return *reinterpret_cast<__half2*>(&r);
}

// ---------------- Kernel 1 (prep): V -> permuted bf16 uint4  +  A_pre ----------------
__global__ void k_prep(const int* __restrict__ tok, const float* __restrict__ emb,
                       const float* __restrict__ U, const float* __restrict__ V,
                       const float* __restrict__ b1, const float* __restrict__ b2) {
    int i = blockIdx.x * blockDim.x + threadIdx.x;
    if (i < VOCAB * 8) {
        int c = i >> 3, j = i & 7;
        int t = j & 3, half = j >> 2;
        __nv_bfloat162 p2 = __floats2bfloat162_rn(V[c * REC + 2 * j], V[c * REC + 2 * j + 1]);
        int p    = c >> 4;
        int w16  = c & 15;
        int tile = (w16 >> 1) & 1;
        int n    = ((w16 >> 2) << 1) | (w16 & 1);
        uint32_t* dst = (uint32_t*)g_Vq;
        dst[(((p * 8 + n) * 4 + t) << 2) + tile * 2 + half] = *reinterpret_cast<uint32_t*>(&p2);
    }
    if (i < NROWS * REC) {
        int rid = i >> 4, r = i & 15;
        int tk  = tok[rid];
        const float* e = emb + (size_t)tk * EMB;
        const float* u = U + r * EMB;
        float acc = b1[r] + b2[r];
        #pragma unroll
        for (int k = 0; k < EMB; k++) acc = fmaf(e[k], u[k], acc);
        g_Apre[i] = acc;
    }
}

// ---------------- Kernel 2: serial recurrence ----------------
__global__ void k_rnn(const float* __restrict__ W, const float* __restrict__ h0v) {
    int lane = threadIdx.x;
    int b = blockIdx.x * 2 + (lane >> 4);
    int r = lane & 15;
    float w[REC];
    #pragma unroll
    for (int j = 0; j < REC; j++) w[j] = W[r * REC + j];
    float h = h0v[r];
    g_hidden[b * REC + r]  = __float2bfloat16(h);
    g_hiddenL[b * REC + r] = __float2bfloat16(h * L2E);
    float anext = g_Apre[b * REC + r];
    for (int t = 0; t < SEQ - 1; t++) {
        float a = anext;
        if (t < SEQ - 2) anext = g_Apre[((t + 1) * BATCH + b) * REC + r];
        float s0 = a, s1 = 0.f, s2 = 0.f, s3 = 0.f;
        #pragma unroll
        for (int j = 0; j < REC; j += 4) {
            float h0_ = __shfl_sync(0xffffffffu, h, j,     16);
            float h1_ = __shfl_sync(0xffffffffu, h, j + 1, 16);
            float h2_ = __shfl_sync(0xffffffffu, h, j + 2, 16);
            float h3_ = __shfl_sync(0xffffffffu, h, j + 3, 16);
            s0 = fmaf(h0_, w[j],     s0);
            s1 = fmaf(h1_, w[j + 1], s1);
            s2 = fmaf(h2_, w[j + 2], s2);
            s3 = fmaf(h3_, w[j + 3], s3);
        }
        float z  = ((s0 + s1) + (s2 + s3)) * (2.0f * L2E);
        float ez = ex2f(z);
        h = 1.0f - 2.0f * rcpf(ez + 1.0f);
        int idx = ((t + 1) * BATCH + b) * REC + r;
        g_hidden[idx]  = __float2bfloat16(h);
        g_hiddenL[idx] = __float2bfloat16(h * L2E);
    }
}

// ---------------- Kernel 3 (pass 1): partial sum exp, NF=4, half2 accumulation ----
// grid (128, VS), 256 thr; warp covers 25 pairs. Flush every 5 pairs.
__global__ void __launch_bounds__(256, 4) k_sum() {
    const int lane = threadIdx.x & 31, warp = threadIdx.x >> 5;
    const int g = lane >> 2, t = lane & 3;
    const int tile  = blockIdx.x * RPB_S;
    const int split = blockIdx.y;

    uint32_t a[NF_S][4];
    {
        const uint32_t* H = (const uint32_t*)g_hiddenL;
        #pragma unroll
        for (int f = 0; f < NF_S; f++) {
            int r0 = tile + f * 16 + g;
            a[f][0] = H[r0 * 8 + t];
            a[f][1] = H[(r0 + 8) * 8 + t];
            a[f][2] = H[r0 * 8 + t + 4];
            a[f][3] = H[(r0 + 8) * 8 + t + 4];
        }
    }

    float s[NF_S][2];
    __half2 hacc[NF_S][2];
    #pragma unroll
    for (int f = 0; f < NF_S; f++) {
        s[f][0] = s[f][1] = 0.f;
        hacc[f][0] = hacc[f][1] = __float2half2_rn(0.f);
    }

    const int p0 = split * (NPAIR / VS) + warp * (NPAIR / VS / 8);
    uint4 b = g_Vq[(p0 * 8 + g) * 4 + t];
    #pragma unroll 1
    for (int blk = 0; blk < 5; blk++) {
        #pragma unroll
        for (int q = 0; q < 5; q++) {
            int p = p0 + blk * 5 + q;
            uint4 bn;
            if (blk * 5 + q < 24) bn = g_Vq[((p + 1) * 8 + g) * 4 + t];
            #pragma unroll
            for (int f = 0; f < NF_S; f++) {
                float d0[4], d1[4];
                mma16816(d0, a[f], b.x, b.y);
                mma16816(d1, a[f], b.z, b.w);
                hacc[f][0] = __hadd2(hacc[f][0], h2ex2(d0[0], d0[1]));
                hacc[f][0] = __hadd2(hacc[f][0], h2ex2(d1[0], d1[1]));
                hacc[f][1] = __hadd2(hacc[f][1], h2ex2(d0[2], d0[3]));
                hacc[f][1] = __hadd2(hacc[f][1], h2ex2(d1[2], d1[3]));
            }
            b = bn;
        }
        #pragma unroll
        for (int f = 0; f < NF_S; f++) {
            float2 f0 = __half22float2(hacc[f][0]);
            float2 f1 = __half22float2(hacc[f][1]);
            s[f][0] += f0.x + f0.y;
            s[f][1] += f1.x + f1.y;
            hacc[f][0] = hacc[f][1] = __float2half2_rn(0.f);
        }
    }
    #pragma unroll
    for (int f = 0; f < NF_S; f++)
        #pragma unroll
        for (int m = 1; m <= 2; m <<= 1) {
            s[f][0] += __shfl_xor_sync(0xffffffffu, s[f][0], m);
            s[f][1] += __shfl_xor_sync(0xffffffffu, s[f][1], m);
        }
    __shared__ float red[8][RPB_S];
    if (t == 0) {
        #pragma unroll
        for (int f = 0; f < NF_S; f++) {
            red[warp][f * 16 + g]     = s[f][0];
            red[warp][f * 16 + g + 8] = s[f][1];
        }
    }
    __syncthreads();
    if (threadIdx.x < RPB_S) {
        float tot = 0.f;
        #pragma unroll
        for (int wq = 0; wq < 8; wq++) tot += red[wq][threadIdx.x];
        g_part[split][tile + threadIdx.x] = tot;
    }
}

// ---------------- Kernel 4 (pass 2): out = logit - ln(sum), float4 stores ----------------
__global__ void __launch_bounds__(256, 5) k_out(float* __restrict__ out) {
    const int lane = threadIdx.x & 31, warp = threadIdx.x >> 5;
    const int g = lane >> 2, t = lane & 3;
    const int tile  = blockIdx.x * RPB_O;
    const int split = blockIdx.y;

    // Precompute the 32 row log-constants once per block.
    __shared__ float sc[RPB_O];
    if (threadIdx.x < RPB_O) {
        float s = 0.f;
        #pragma unroll
        for (int q = 0; q < VS; q++) s += g_part[q][tile + threadIdx.x];
        sc[threadIdx.x] = LN2 * lg2f(s);
    }

    uint32_t a[NF_O][4];
    {
        const uint32_t* H = (const uint32_t*)g_hidden;
        #pragma unroll
        for (int f = 0; f < NF_O; f++) {
            int r0 = tile + f * 16 + g;
            a[f][0] = H[r0 * 8 + t];
            a[f][1] = H[(r0 + 8) * 8 + t];
            a[f][2] = H[r0 * 8 + t + 4];
            a[f][3] = H[(r0 + 8) * 8 + t + 4];
        }
    }
    __syncthreads();

    float nc[NF_O][2];
    #pragma unroll
    for (int f = 0; f < NF_O; f++) {
        nc[f][0] = -sc[f * 16 + g];
        nc[f][1] = -sc[f * 16 + g + 8];
    }
    float* base = out + (size_t)(tile + g) * VOCAB + 4 * t;

    const int p0 = split * (NPAIR / VS) + warp * (NPAIR / VS / 8);
    const int pend = p0 + (NPAIR / VS / 8);
    uint4 b = g_Vq[(p0 * 8 + g) * 4 + t];
    for (int p = p0; p < pend; p++) {
        uint4 bn;
        if (p + 1 < pend) bn = g_Vq[((p + 1) * 8 + g) * 4 + t];
        float* bp = base + p * 16;
        #pragma unroll
        for (int f = 0; f < NF_O; f++) {
            float d0[4], d1[4];
            mma16816c(d0, a[f], b.x, b.y, nc[f][0], nc[f][1]);
            mma16816c(d1, a[f], b.z, b.w, nc[f][0], nc[f][1]);
            __stcs((float4*)(bp + (size_t)(f * 16)     * VOCAB),
                   make_float4(d0[0], d0[1], d1[0], d1[1]));
            __stcs((float4*)(bp + (size_t)(f * 16 + 8) * VOCAB),
                   make_float4(d0[2], d0[3], d1[2], d1[3]));
        }
        b = bn;
    }
}

extern "C" void kernel_launch(void* const* d_in, const int* in_sizes, int n_in,
                              void* d_out, int out_size) {
    const int*   tok = (const int*)d_in[0];
    const float* emb = (const float*)d_in[1];
    const float* U   = (const float*)d_in[2];
    const float* W   = (const float*)d_in[3];
    const float* V   = (const float*)d_in[4];
    const float* b1  = (const float*)d_in[5];
    const float* b2  = (const float*)d_in[6];
    const float* h0  = (const float*)d_in[7];
    float* out = (float*)d_out;

    k_prep<<<(VOCAB * 8 + 255) / 256, 256>>>(tok, emb, U, V, b1, b2);
    k_rnn<<<BATCH / 2, 32>>>(W, h0);
    dim3 gs(NROWS / RPB_S, VS);
    k_sum<<<gs, 256>>>();
    dim3 go(NROWS / RPB_O, VS);
    k_out<<<go, 256>>>(out);
}